// round 7
// baseline (speedup 1.0000x reference)
#include <cuda_runtime.h>
#include <math.h>

#define T_TOK 4096   // B*L tokens
#define DDIM  2048   // hidden dim
#define NEXP  8      // experts
#define IMOE  768    // expert intermediate
#define ISH   4096   // shared expert intermediate

// ---------------- device scratch (static, no allocations) ----------------
__device__ float g_act_shared[(size_t)T_TOK * ISH];            // tf32 bits
__device__ float g_act_moe[(size_t)NEXP * T_TOK * IMOE];       // tf32 bits
__device__ int   g_idx[NEXP * T_TOK];
__device__ float g_cw[NEXP * T_TOK];
__device__ int   g_cnt[NEXP];
__device__ float g_sgate[T_TOK];

// ---------------- helpers ----------------
__device__ __forceinline__ float silu_f(float x) { return x / (1.f + expf(-x)); }

__device__ __forceinline__ unsigned f2tf(float x) {
    unsigned u;
    asm("cvt.rna.tf32.f32 %0, %1;" : "=r"(u) : "f"(x));
    return u;
}
// rna-convert 4 raw-fp32 bit registers in place
__device__ __forceinline__ void tf4(unsigned* r) {
    r[0] = f2tf(__uint_as_float(r[0]));
    r[1] = f2tf(__uint_as_float(r[1]));
    r[2] = f2tf(__uint_as_float(r[2]));
    r[3] = f2tf(__uint_as_float(r[3]));
}
__device__ __forceinline__ void tf2(unsigned* r) {
    r[0] = f2tf(__uint_as_float(r[0]));
    r[1] = f2tf(__uint_as_float(r[1]));
}
__device__ __forceinline__ void ldsm4(unsigned& r0, unsigned& r1,
                                      unsigned& r2, unsigned& r3, unsigned addr) {
    asm volatile("ldmatrix.sync.aligned.m8n8.x4.shared.b16 {%0,%1,%2,%3}, [%4];"
                 : "=r"(r0), "=r"(r1), "=r"(r2), "=r"(r3) : "r"(addr));
}
__device__ __forceinline__ void mma8(float* c, const unsigned* a, const unsigned* b) {
    asm volatile("mma.sync.aligned.m16n8k8.row.col.f32.tf32.tf32.f32 "
                 "{%0,%1,%2,%3}, {%4,%5,%6,%7}, {%8,%9}, {%0,%1,%2,%3};"
                 : "+f"(c[0]), "+f"(c[1]), "+f"(c[2]), "+f"(c[3])
                 : "r"(a[0]), "r"(a[1]), "r"(a[2]), "r"(a[3]),
                   "r"(b[0]), "r"(b[1]));
}
__device__ __forceinline__ void cp16(unsigned dst, const void* src) {
    asm volatile("cp.async.cg.shared.global [%0], [%1], 16;"
                 :: "r"(dst), "l"(src) : "memory");
}
__device__ __forceinline__ void cp16z(unsigned dst, const void* src, int sz) {
    asm volatile("cp.async.cg.shared.global [%0], [%1], 16, %2;"
                 :: "r"(dst), "l"(src), "r"(sz) : "memory");
}
#define CP_COMMIT() asm volatile("cp.async.commit_group;" ::: "memory")
#define CP_WAIT2()  asm volatile("cp.async.wait_group 2;" ::: "memory")
#define CP_WAIT1()  asm volatile("cp.async.wait_group 1;" ::: "memory")
#define CP_WAIT0()  asm volatile("cp.async.wait_group 0;" ::: "memory")

// XOR-swizzled 16B-chunk index for a [rows x 32-float] k-tile (8 chunks/row)
__device__ __forceinline__ int swz(int row, int chunk) {
    return row * 8 + (chunk ^ (row & 7));
}

// ---------------- small kernels ----------------
__global__ void zero_cnt_kernel() {
    if (threadIdx.x < NEXP) g_cnt[threadIdx.x] = 0;
}

__global__ void router_kernel(const float* __restrict__ h,
                              const float* __restrict__ gate_w,
                              const float* __restrict__ seg_w) {
    int t = blockIdx.x;
    int tid = threadIdx.x;               // 128 threads
    float acc[9];
#pragma unroll
    for (int e = 0; e < 9; e++) acc[e] = 0.f;
    const float* hp = h + (size_t)t * DDIM;
    for (int d = tid; d < DDIM; d += 128) {
        float hv = hp[d];
#pragma unroll
        for (int e = 0; e < 8; e++) acc[e] += hv * gate_w[e * DDIM + d];
        acc[8] += hv * seg_w[d];
    }
#pragma unroll
    for (int e = 0; e < 9; e++) {
#pragma unroll
        for (int off = 16; off > 0; off >>= 1)
            acc[e] += __shfl_down_sync(0xffffffffu, acc[e], off);
    }
    __shared__ float s[9][4];
    int warp = tid >> 5, lane = tid & 31;
    if (lane == 0) {
#pragma unroll
        for (int e = 0; e < 9; e++) s[e][warp] = acc[e];
    }
    __syncthreads();
    if (tid == 0) {
        float logits[9];
#pragma unroll
        for (int e = 0; e < 9; e++)
            logits[e] = s[e][0] + s[e][1] + s[e][2] + s[e][3];
        int i1 = 0; float l1 = logits[0];
#pragma unroll
        for (int e = 1; e < 8; e++)
            if (logits[e] > l1) { l1 = logits[e]; i1 = e; }
        int i2 = -1; float l2 = -3.0e38f;
#pragma unroll
        for (int e = 0; e < 8; e++)
            if (e != i1 && logits[e] > l2) { l2 = logits[e]; i2 = e; }
        float w1 = 1.f / (1.f + expf(l2 - l1));
        float w2 = 1.f - w1;
        int r1 = atomicAdd(&g_cnt[i1], 1);
        g_idx[i1 * T_TOK + r1] = t;  g_cw[i1 * T_TOK + r1] = w1;
        int r2 = atomicAdd(&g_cnt[i2], 1);
        g_idx[i2 * T_TOK + r2] = t;  g_cw[i2 * T_TOK + r2] = w2;
        g_sgate[t] = 1.f / (1.f + expf(-logits[8]));
    }
}

// ============= fused gate/up GEMM (tf32, cp.async 3-stage, 2 CTAs/SM) =============
// Raw fp32 operands; rna->tf32 applied in registers after ldmatrix.
// Block: 128M x 64N (per matrix). Warps 4(M) x 2(N): warp tile 32x32 per matrix.
// Stage layout: [A: 16KB][G: 8KB][U: 8KB] = 32KB; 3 stages = 96KB.
template<bool GATHER>
__global__ void __launch_bounds__(256, 2)
gemm_gateup_t(const float* __restrict__ A,
              const float* __restrict__ Bg_base,
              const float* __restrict__ Bu_base,
              long long strideB, int Kd)
{
    extern __shared__ unsigned smem[];
    const int e  = blockIdx.z;
    const int M  = GATHER ? g_cnt[e] : T_TOK;
    const int m0 = blockIdx.y * 128;
    if (m0 >= M) return;
    const int n0 = blockIdx.x * 64;

    const float* Bg = Bg_base + (long long)e * strideB;
    const float* Bu = Bu_base + (long long)e * strideB;
    float* C; int ldc;
    if (GATHER) { C = g_act_moe + (long long)e * T_TOK * IMOE; ldc = IMOE; }
    else        { C = g_act_shared;                            ldc = ISH;  }

    const unsigned sbase = (unsigned)__cvta_generic_to_shared(smem);
    const int tid = threadIdx.x, lane = tid & 31, wid = tid >> 5;
    const int wm = (wid & 3) * 32, wn = (wid >> 2) * 32;

    // cp.async source/dst setup
    const float* asrc[4]; int asz[4]; unsigned adst[4];
#pragma unroll
    for (int i = 0; i < 4; i++) {
        int id = tid + i * 256, row = id >> 3, ch = id & 7;
        int r = m0 + row;
        bool v = GATHER ? (r < M) : true;
        asrc[i] = v ? A + (size_t)(GATHER ? g_idx[e * T_TOK + r] : r) * Kd + ch * 4 : A;
        asz[i]  = v ? 16 : 0;
        adst[i] = swz(row, ch) * 16;
    }
    const float* gsrc[2]; const float* usrc[2]; unsigned bdst[2];
#pragma unroll
    for (int i = 0; i < 2; i++) {
        int id = tid + i * 256, row = id >> 3, ch = id & 7;
        gsrc[i] = Bg + (size_t)(n0 + row) * Kd + ch * 4;
        usrc[i] = Bu + (size_t)(n0 + row) * Kd + ch * 4;
        bdst[i] = swz(row, ch) * 16;
    }

    auto issue = [&](int s) {
        unsigned sb = sbase + (s % 3) * 32768;
        int koff = s * 32;
#pragma unroll
        for (int i = 0; i < 4; i++) cp16z(sb + adst[i], asrc[i] + koff, asz[i]);
#pragma unroll
        for (int i = 0; i < 2; i++) cp16(sb + 16384 + bdst[i], gsrc[i] + koff);
#pragma unroll
        for (int i = 0; i < 2; i++) cp16(sb + 24576 + bdst[i], usrc[i] + koff);
    };

    // precomputed fragment offsets
    const int sub = lane >> 3, rr = lane & 7;
    unsigned offA[4][2], offB[4][2];
#pragma unroll
    for (int ks = 0; ks < 4; ks++) {
#pragma unroll
        for (int mt = 0; mt < 2; mt++)
            offA[ks][mt] = swz(wm + mt * 16 + (sub & 1) * 8 + rr, 2 * ks + (sub >> 1)) * 16;
#pragma unroll
        for (int jg = 0; jg < 2; jg++)
            offB[ks][jg] = swz(wn + (jg * 2 + (sub >> 1)) * 8 + rr, 2 * ks + (sub & 1)) * 16;
    }

    float cg[2][4][4] = {}, cu[2][4][4] = {};
    const int S = Kd / 32;

    issue(0); CP_COMMIT();
    issue(1); CP_COMMIT();

#pragma unroll 1
    for (int s = 0; s < S; s++) {
        if (s + 1 < S) { CP_WAIT1(); } else { CP_WAIT0(); }
        __syncthreads();
        unsigned sb = sbase + (s % 3) * 32768;
#pragma unroll
        for (int ks = 0; ks < 4; ks++) {
            unsigned a[2][4], bg[4][2], bu[4][2];
#pragma unroll
            for (int mt = 0; mt < 2; mt++) {
                ldsm4(a[mt][0], a[mt][1], a[mt][2], a[mt][3], sb + offA[ks][mt]);
                tf4(a[mt]);
            }
#pragma unroll
            for (int jg = 0; jg < 2; jg++) {
                ldsm4(bg[2*jg][0], bg[2*jg][1], bg[2*jg+1][0], bg[2*jg+1][1],
                      sb + 16384 + offB[ks][jg]);
                tf2(bg[2*jg]); tf2(bg[2*jg+1]);
                ldsm4(bu[2*jg][0], bu[2*jg][1], bu[2*jg+1][0], bu[2*jg+1][1],
                      sb + 24576 + offB[ks][jg]);
                tf2(bu[2*jg]); tf2(bu[2*jg+1]);
            }
#pragma unroll
            for (int mt = 0; mt < 2; mt++)
#pragma unroll
                for (int nt = 0; nt < 4; nt++) {
                    mma8(cg[mt][nt], a[mt], bg[nt]);
                    mma8(cu[mt][nt], a[mt], bu[nt]);
                }
        }
        if (s + 2 < S) { issue(s + 2); CP_COMMIT(); }
    }

    // epilogue: silu(g)*u, stored as tf32 bits (down GEMM A-side needs no cvt)
    const int rr2 = lane >> 2, cc = (lane & 3) * 2;
#pragma unroll
    for (int mt = 0; mt < 2; mt++) {
#pragma unroll
        for (int h2 = 0; h2 < 2; h2++) {
            int r = m0 + wm + mt * 16 + rr2 + h2 * 8;
            if (GATHER && r >= M) continue;
            float* crow = C + (size_t)r * ldc + n0 + wn;
#pragma unroll
            for (int nt = 0; nt < 4; nt++) {
                float v0 = silu_f(cg[mt][nt][2*h2+0]) * cu[mt][nt][2*h2+0];
                float v1 = silu_f(cg[mt][nt][2*h2+1]) * cu[mt][nt][2*h2+1];
                float2 v = make_float2(__uint_as_float(f2tf(v0)),
                                       __uint_as_float(f2tf(v1)));
                *(float2*)(crow + nt * 8 + cc) = v;
            }
        }
    }
}

// ============= down GEMM (tf32, cp.async 4-stage, 2 CTAs/SM) =============
// A = activations (already tf32 bits, no cvt). B = raw fp32 weights, cvt in regs.
// Block: 128M x 64N. Warps 4(M) x 2(N): warp tile 32x32.
// Stage layout: [A: 16KB][B: 8KB] = 24KB; 4 stages = 96KB.
template<bool MOE>
__global__ void __launch_bounds__(256, 2)
gemm_down_t(const float* __restrict__ Bbase, long long strideB,
            float* __restrict__ out, int Kd)
{
    extern __shared__ unsigned smem[];
    const int e  = blockIdx.z;
    const int M  = MOE ? g_cnt[e] : T_TOK;
    const int m0 = blockIdx.y * 128;
    if (m0 >= M) return;
    const int n0 = blockIdx.x * 64;

    const float* A; int lda;
    if (MOE) { A = g_act_moe + (size_t)e * T_TOK * IMOE; lda = IMOE; }
    else     { A = g_act_shared;                         lda = ISH;  }
    const float* B = Bbase + (long long)e * strideB;

    const unsigned sbase = (unsigned)__cvta_generic_to_shared(smem);
    const int tid = threadIdx.x, lane = tid & 31, wid = tid >> 5;
    const int wm = (wid & 3) * 32, wn = (wid >> 2) * 32;

    const float* asrc[4]; int asz[4]; unsigned adst[4];
#pragma unroll
    for (int i = 0; i < 4; i++) {
        int id = tid + i * 256, row = id >> 3, ch = id & 7;
        int r = m0 + row;
        bool v = (r < M);
        asrc[i] = v ? A + (size_t)r * lda + ch * 4 : A;
        asz[i]  = v ? 16 : 0;
        adst[i] = swz(row, ch) * 16;
    }
    const float* bsrc[2]; unsigned bdst[2];
#pragma unroll
    for (int i = 0; i < 2; i++) {
        int id = tid + i * 256, row = id >> 3, ch = id & 7;
        bsrc[i] = B + (size_t)(n0 + row) * Kd + ch * 4;
        bdst[i] = swz(row, ch) * 16;
    }

    auto issue = [&](int s) {
        unsigned sb = sbase + (s & 3) * 24576;
        int koff = s * 32;
#pragma unroll
        for (int i = 0; i < 4; i++) cp16z(sb + adst[i], asrc[i] + koff, asz[i]);
#pragma unroll
        for (int i = 0; i < 2; i++) cp16(sb + 16384 + bdst[i], bsrc[i] + koff);
    };

    const int sub = lane >> 3, rr = lane & 7;
    unsigned offA[4][2], offB[4][2];
#pragma unroll
    for (int ks = 0; ks < 4; ks++) {
#pragma unroll
        for (int mt = 0; mt < 2; mt++)
            offA[ks][mt] = swz(wm + mt * 16 + (sub & 1) * 8 + rr, 2 * ks + (sub >> 1)) * 16;
#pragma unroll
        for (int jg = 0; jg < 2; jg++)
            offB[ks][jg] = swz(wn + (jg * 2 + (sub >> 1)) * 8 + rr, 2 * ks + (sub & 1)) * 16;
    }

    float c[2][4][4] = {};
    const int S = Kd / 32;

    issue(0); CP_COMMIT();
    issue(1); CP_COMMIT();
    issue(2); CP_COMMIT();

#pragma unroll 1
    for (int s = 0; s < S; s++) {
        int rem = S - s;
        if (rem >= 3)      { CP_WAIT2(); }
        else if (rem == 2) { CP_WAIT1(); }
        else               { CP_WAIT0(); }
        __syncthreads();
        unsigned sb = sbase + (s & 3) * 24576;
#pragma unroll
        for (int ks = 0; ks < 4; ks++) {
            unsigned a[2][4], bb[4][2];
#pragma unroll
            for (int mt = 0; mt < 2; mt++)
                ldsm4(a[mt][0], a[mt][1], a[mt][2], a[mt][3], sb + offA[ks][mt]);
#pragma unroll
            for (int jg = 0; jg < 2; jg++) {
                ldsm4(bb[2*jg][0], bb[2*jg][1], bb[2*jg+1][0], bb[2*jg+1][1],
                      sb + 16384 + offB[ks][jg]);
                tf2(bb[2*jg]); tf2(bb[2*jg+1]);
            }
#pragma unroll
            for (int mt = 0; mt < 2; mt++)
#pragma unroll
                for (int nt = 0; nt < 4; nt++)
                    mma8(c[mt][nt], a[mt], bb[nt]);
        }
        if (s + 3 < S) { issue(s + 3); CP_COMMIT(); }
    }

    const int rr2 = lane >> 2, cc = (lane & 3) * 2;
    if (MOE) {
#pragma unroll
        for (int mt = 0; mt < 2; mt++) {
#pragma unroll
            for (int h2 = 0; h2 < 2; h2++) {
                int r = m0 + wm + mt * 16 + rr2 + h2 * 8;
                if (r >= M) continue;
                int tok = g_idx[e * T_TOK + r];
                float w  = g_cw[e * T_TOK + r];
                float* orow = out + (size_t)tok * DDIM + n0 + wn;
#pragma unroll
                for (int nt = 0; nt < 4; nt++) {
                    atomicAdd(&orow[nt * 8 + cc + 0], w * c[mt][nt][2*h2+0]);
                    atomicAdd(&orow[nt * 8 + cc + 1], w * c[mt][nt][2*h2+1]);
                }
            }
        }
    } else {
#pragma unroll
        for (int mt = 0; mt < 2; mt++) {
#pragma unroll
            for (int h2 = 0; h2 < 2; h2++) {
                int r = m0 + wm + mt * 16 + rr2 + h2 * 8;
                float sg = g_sgate[r];
                float* orow = out + (size_t)r * DDIM + n0 + wn;
#pragma unroll
                for (int nt = 0; nt < 4; nt++) {
                    float2 v = make_float2(sg * c[mt][nt][2*h2+0],
                                           sg * c[mt][nt][2*h2+1]);
                    *(float2*)(orow + nt * 8 + cc) = v;
                }
            }
        }
    }
}

// ---------------- launch ----------------
extern "C" void kernel_launch(void* const* d_in, const int* in_sizes, int n_in,
                              void* d_out, int out_size) {
    const float* h    = (const float*)d_in[0];  // [T, D]
    const float* gw   = (const float*)d_in[1];  // [E, D]
    const float* gup  = (const float*)d_in[2];  // [E, 2I, D]
    const float* dwn  = (const float*)d_in[3];  // [E, D, I]
    const float* sgw  = (const float*)d_in[4];  // [IS, D]
    const float* suw  = (const float*)d_in[5];  // [IS, D]
    const float* sdw  = (const float*)d_in[6];  // [D, IS]
    const float* segw = (const float*)d_in[7];  // [1, D]
    float* out = (float*)d_out;

    const int SMEM_GU = 98304;   // 96KB (3 x 32KB); 2 CTAs/SM = 192KB <= 228KB
    const int SMEM_DN = 98304;   // 96KB (4 x 24KB)

    static bool init_done = false;
    if (!init_done) {
        cudaFuncSetAttribute(gemm_gateup_t<true>,  cudaFuncAttributeMaxDynamicSharedMemorySize, SMEM_GU);
        cudaFuncSetAttribute(gemm_gateup_t<false>, cudaFuncAttributeMaxDynamicSharedMemorySize, SMEM_GU);
        cudaFuncSetAttribute(gemm_down_t<true>,    cudaFuncAttributeMaxDynamicSharedMemorySize, SMEM_DN);
        cudaFuncSetAttribute(gemm_down_t<false>,   cudaFuncAttributeMaxDynamicSharedMemorySize, SMEM_DN);
        init_done = true;
    }

    zero_cnt_kernel<<<1, 32>>>();
    router_kernel<<<T_TOK, 128>>>(h, gw, segw);

    // MoE gate/up (gathered) — raw fp32 inputs, cvt in-register
    gemm_gateup_t<true><<<dim3(IMOE / 64, T_TOK / 128, NEXP), 256, SMEM_GU>>>(
        h, gup, gup + (size_t)IMOE * DDIM, (long long)2 * IMOE * DDIM, DDIM);

    // shared gate/up
    gemm_gateup_t<false><<<dim3(ISH / 64, T_TOK / 128, 1), 256, SMEM_GU>>>(
        h, sgw, suw, 0LL, DDIM);

    // shared down (writes every output element)
    gemm_down_t<false><<<dim3(DDIM / 64, T_TOK / 128, 1), 256, SMEM_DN>>>(
        sdw, 0LL, out, ISH);

    // MoE down (atomic accumulate)
    gemm_down_t<true><<<dim3(DDIM / 64, T_TOK / 128, NEXP), 256, SMEM_DN>>>(
        dwn, (long long)DDIM * IMOE, out, IMOE);
}

// round 8
// speedup vs baseline: 1.0983x; 1.0983x over previous
#include <cuda_runtime.h>
#include <math.h>

#define T_TOK 4096   // B*L tokens
#define DDIM  2048   // hidden dim
#define NEXP  8      // experts
#define IMOE  768    // expert intermediate
#define ISH   4096   // shared expert intermediate

// ---------------- device scratch (static, no allocations) ----------------
__device__ float g_act_shared[(size_t)T_TOK * ISH];            // tf32 bits
__device__ float g_act_moe[(size_t)NEXP * T_TOK * IMOE];       // tf32 bits
__device__ int   g_idx[NEXP * T_TOK];
__device__ float g_cw[NEXP * T_TOK];
__device__ int   g_cnt[NEXP];
__device__ float g_sgate[T_TOK];
// tf32-converted operands
__device__ float g_h_tf[(size_t)T_TOK * DDIM];
__device__ float g_gup_tf[(size_t)NEXP * 2 * IMOE * DDIM];
__device__ float g_dwn_tf[(size_t)NEXP * DDIM * IMOE];
__device__ float g_sgw_tf[(size_t)ISH * DDIM];
__device__ float g_suw_tf[(size_t)ISH * DDIM];
__device__ float g_sdw_tf[(size_t)DDIM * ISH];

// ---------------- helpers ----------------
__device__ __forceinline__ float silu_f(float x) { return x / (1.f + expf(-x)); }

__device__ __forceinline__ unsigned f2tf(float x) {
    unsigned u;
    asm("cvt.rna.tf32.f32 %0, %1;" : "=r"(u) : "f"(x));
    return u;
}
__device__ __forceinline__ void ldsm4(unsigned& r0, unsigned& r1,
                                      unsigned& r2, unsigned& r3, unsigned addr) {
    asm volatile("ldmatrix.sync.aligned.m8n8.x4.shared.b16 {%0,%1,%2,%3}, [%4];"
                 : "=r"(r0), "=r"(r1), "=r"(r2), "=r"(r3) : "r"(addr));
}
__device__ __forceinline__ void mma8(float* c, const unsigned* a, const unsigned* b) {
    asm volatile("mma.sync.aligned.m16n8k8.row.col.f32.tf32.tf32.f32 "
                 "{%0,%1,%2,%3}, {%4,%5,%6,%7}, {%8,%9}, {%0,%1,%2,%3};"
                 : "+f"(c[0]), "+f"(c[1]), "+f"(c[2]), "+f"(c[3])
                 : "r"(a[0]), "r"(a[1]), "r"(a[2]), "r"(a[3]),
                   "r"(b[0]), "r"(b[1]));
}
__device__ __forceinline__ void cp16(unsigned dst, const void* src) {
    asm volatile("cp.async.cg.shared.global [%0], [%1], 16;"
                 :: "r"(dst), "l"(src) : "memory");
}
__device__ __forceinline__ void cp16z(unsigned dst, const void* src, int sz) {
    asm volatile("cp.async.cg.shared.global [%0], [%1], 16, %2;"
                 :: "r"(dst), "l"(src), "r"(sz) : "memory");
}
#define CP_COMMIT() asm volatile("cp.async.commit_group;" ::: "memory")
#define CP_WAIT1()  asm volatile("cp.async.wait_group 1;" ::: "memory")
#define CP_WAIT0()  asm volatile("cp.async.wait_group 0;" ::: "memory")

// vectorized global float2 atomic add (sm_90+)
__device__ __forceinline__ void red2(float* a, float x, float y) {
    asm volatile("red.global.add.v2.f32 [%0], {%1,%2};"
                 :: "l"(a), "f"(x), "f"(y) : "memory");
}

// XOR-swizzled 16B-chunk index for a [rows x 32-float] k-tile (8 chunks/row)
__device__ __forceinline__ int swz(int row, int chunk) {
    return row * 8 + (chunk ^ (row & 7));
}

// ---------------- small kernels ----------------
__global__ void zero_cnt_kernel() {
    if (threadIdx.x < NEXP) g_cnt[threadIdx.x] = 0;
}

// Fused prep: grid (4096, 7). y<6 = tf32 conversion slices; y==6 = router.
__global__ void prep_kernel(const float* __restrict__ h,
                            const float* __restrict__ gup,
                            const float* __restrict__ dwn,
                            const float* __restrict__ sgw,
                            const float* __restrict__ suw,
                            const float* __restrict__ sdw,
                            const float* __restrict__ gw,
                            const float* __restrict__ segw) {
    const int tid = threadIdx.x;   // 256
    if (blockIdx.y < 6) {
        const float4* src; float4* dst; size_t n4;
        switch (blockIdx.y) {
            case 0: src=(const float4*)h;   dst=(float4*)g_h_tf;   n4=(size_t)T_TOK*DDIM/4; break;
            case 1: src=(const float4*)gup; dst=(float4*)g_gup_tf; n4=(size_t)NEXP*2*IMOE*DDIM/4; break;
            case 2: src=(const float4*)dwn; dst=(float4*)g_dwn_tf; n4=(size_t)NEXP*DDIM*IMOE/4; break;
            case 3: src=(const float4*)sgw; dst=(float4*)g_sgw_tf; n4=(size_t)ISH*DDIM/4; break;
            case 4: src=(const float4*)suw; dst=(float4*)g_suw_tf; n4=(size_t)ISH*DDIM/4; break;
            default:src=(const float4*)sdw; dst=(float4*)g_sdw_tf; n4=(size_t)DDIM*ISH/4; break;
        }
        size_t i = (size_t)blockIdx.x * 256 + tid;
        size_t stride = (size_t)gridDim.x * 256;
        for (; i < n4; i += stride) {
            float4 v = src[i];
            uint4 q = make_uint4(f2tf(v.x), f2tf(v.y), f2tf(v.z), f2tf(v.w));
            ((uint4*)dst)[i] = q;
        }
        return;
    }
    // ---- router (one block per token, 256 threads) ----
    const int t = blockIdx.x;
    float acc[9];
#pragma unroll
    for (int e = 0; e < 9; e++) acc[e] = 0.f;
    const float* hp = h + (size_t)t * DDIM;
    for (int d = tid; d < DDIM; d += 256) {
        float hv = hp[d];
#pragma unroll
        for (int e = 0; e < 8; e++) acc[e] += hv * gw[e * DDIM + d];
        acc[8] += hv * segw[d];
    }
#pragma unroll
    for (int e = 0; e < 9; e++) {
#pragma unroll
        for (int off = 16; off > 0; off >>= 1)
            acc[e] += __shfl_down_sync(0xffffffffu, acc[e], off);
    }
    __shared__ float s[9][8];
    int warp = tid >> 5, lane = tid & 31;
    if (lane == 0) {
#pragma unroll
        for (int e = 0; e < 9; e++) s[e][warp] = acc[e];
    }
    __syncthreads();
    if (tid == 0) {
        float logits[9];
#pragma unroll
        for (int e = 0; e < 9; e++) {
            float v = 0.f;
#pragma unroll
            for (int w2 = 0; w2 < 8; w2++) v += s[e][w2];
            logits[e] = v;
        }
        int i1 = 0; float l1 = logits[0];
#pragma unroll
        for (int e = 1; e < 8; e++)
            if (logits[e] > l1) { l1 = logits[e]; i1 = e; }
        int i2 = -1; float l2 = -3.0e38f;
#pragma unroll
        for (int e = 0; e < 8; e++)
            if (e != i1 && logits[e] > l2) { l2 = logits[e]; i2 = e; }
        float w1 = 1.f / (1.f + expf(l2 - l1));
        float w2 = 1.f - w1;
        int r1 = atomicAdd(&g_cnt[i1], 1);
        g_idx[i1 * T_TOK + r1] = t;  g_cw[i1 * T_TOK + r1] = w1;
        int r2 = atomicAdd(&g_cnt[i2], 1);
        g_idx[i2 * T_TOK + r2] = t;  g_cw[i2 * T_TOK + r2] = w2;
        g_sgate[t] = 1.f / (1.f + expf(-logits[8]));
    }
}

// ============= fused gate/up GEMM (MoE + shared in one launch) =============
// 1D grid: blocks [0,3072) = MoE (e = bid/384; 32 m-tiles x 12 n-tiles),
//          blocks [3072,5120) = shared (32 m-tiles x 64 n-tiles).
// Block: 128M x 64N per matrix; warps 4(M) x 2(N); 3-stage cp.async; 2 CTAs/SM.
// Stage: [A 16KB][G 8KB][U 8KB] = 32KB; 3 stages = 96KB.
__global__ void __launch_bounds__(256, 2)
gateup_fused()
{
    extern __shared__ unsigned smem[];
    const int bid = blockIdx.x;
    const bool gather = (bid < 3072);
    int e = 0, my, nx;
    if (gather) { e = bid / 384; int r = bid % 384; my = r / 12; nx = r % 12; }
    else        { int r = bid - 3072; my = r / 64; nx = r % 64; }

    const int M  = gather ? g_cnt[e] : T_TOK;
    const int m0 = my * 128;
    if (m0 >= M) return;
    const int n0 = nx * 64;

    const float *Bg, *Bu; float* C; int ldc;
    if (gather) {
        Bg = g_gup_tf + (size_t)e * 2 * IMOE * DDIM;
        Bu = Bg + (size_t)IMOE * DDIM;
        C  = g_act_moe + (size_t)e * T_TOK * IMOE;  ldc = IMOE;
    } else {
        Bg = g_sgw_tf;  Bu = g_suw_tf;
        C  = g_act_shared;  ldc = ISH;
    }

    const unsigned sbase = (unsigned)__cvta_generic_to_shared(smem);
    const int tid = threadIdx.x, lane = tid & 31, wid = tid >> 5;
    const int wm = (wid & 3) * 32, wn = (wid >> 2) * 32;

    const float* asrc[4]; int asz[4]; unsigned adst[4];
#pragma unroll
    for (int i = 0; i < 4; i++) {
        int id = tid + i * 256, row = id >> 3, ch = id & 7;
        int r = m0 + row;
        bool v = gather ? (r < M) : true;
        const float* arow;
        if (gather) arow = v ? g_h_tf + (size_t)g_idx[e * T_TOK + r] * DDIM : g_h_tf;
        else        arow = g_h_tf + (size_t)r * DDIM;
        asrc[i] = arow + ch * 4;
        asz[i]  = v ? 16 : 0;
        adst[i] = swz(row, ch) * 16;
    }
    const float* gsrc[2]; const float* usrc[2]; unsigned bdst[2];
#pragma unroll
    for (int i = 0; i < 2; i++) {
        int id = tid + i * 256, row = id >> 3, ch = id & 7;
        gsrc[i] = Bg + (size_t)(n0 + row) * DDIM + ch * 4;
        usrc[i] = Bu + (size_t)(n0 + row) * DDIM + ch * 4;
        bdst[i] = swz(row, ch) * 16;
    }

    auto issue = [&](int s) {
        unsigned sb = sbase + (s % 3) * 32768;
        int koff = s * 32;
#pragma unroll
        for (int i = 0; i < 4; i++) cp16z(sb + adst[i], asrc[i] + koff, asz[i]);
#pragma unroll
        for (int i = 0; i < 2; i++) cp16(sb + 16384 + bdst[i], gsrc[i] + koff);
#pragma unroll
        for (int i = 0; i < 2; i++) cp16(sb + 24576 + bdst[i], usrc[i] + koff);
    };

    const int sub = lane >> 3, rr = lane & 7;
    unsigned offA[4][2], offB[4][2];
#pragma unroll
    for (int ks = 0; ks < 4; ks++) {
#pragma unroll
        for (int mt = 0; mt < 2; mt++)
            offA[ks][mt] = swz(wm + mt * 16 + (sub & 1) * 8 + rr, 2 * ks + (sub >> 1)) * 16;
#pragma unroll
        for (int jg = 0; jg < 2; jg++)
            offB[ks][jg] = swz(wn + (jg * 2 + (sub >> 1)) * 8 + rr, 2 * ks + (sub & 1)) * 16;
    }

    float cg[2][4][4] = {}, cu[2][4][4] = {};
    const int S = DDIM / 32;

    issue(0); CP_COMMIT();
    issue(1); CP_COMMIT();

#pragma unroll 1
    for (int s = 0; s < S; s++) {
        if (s + 1 < S) { CP_WAIT1(); } else { CP_WAIT0(); }
        __syncthreads();
        unsigned sb = sbase + (s % 3) * 32768;
#pragma unroll
        for (int ks = 0; ks < 4; ks++) {
            unsigned a[2][4], bg[4][2], bu[4][2];
#pragma unroll
            for (int mt = 0; mt < 2; mt++)
                ldsm4(a[mt][0], a[mt][1], a[mt][2], a[mt][3], sb + offA[ks][mt]);
#pragma unroll
            for (int jg = 0; jg < 2; jg++) {
                ldsm4(bg[2*jg][0], bg[2*jg][1], bg[2*jg+1][0], bg[2*jg+1][1],
                      sb + 16384 + offB[ks][jg]);
                ldsm4(bu[2*jg][0], bu[2*jg][1], bu[2*jg+1][0], bu[2*jg+1][1],
                      sb + 24576 + offB[ks][jg]);
            }
#pragma unroll
            for (int mt = 0; mt < 2; mt++)
#pragma unroll
                for (int nt = 0; nt < 4; nt++) {
                    mma8(cg[mt][nt], a[mt], bg[nt]);
                    mma8(cu[mt][nt], a[mt], bu[nt]);
                }
        }
        if (s + 2 < S) { issue(s + 2); CP_COMMIT(); }
    }

    // epilogue: silu(g)*u as tf32 bits (down GEMM A-side needs no cvt)
    const int rr2 = lane >> 2, cc = (lane & 3) * 2;
#pragma unroll
    for (int mt = 0; mt < 2; mt++) {
#pragma unroll
        for (int h2 = 0; h2 < 2; h2++) {
            int r = m0 + wm + mt * 16 + rr2 + h2 * 8;
            if (gather && r >= M) continue;
            float* crow = C + (size_t)r * ldc + n0 + wn;
#pragma unroll
            for (int nt = 0; nt < 4; nt++) {
                float v0 = silu_f(cg[mt][nt][2*h2+0]) * cu[mt][nt][2*h2+0];
                float v1 = silu_f(cg[mt][nt][2*h2+1]) * cu[mt][nt][2*h2+1];
                float2 v = make_float2(__uint_as_float(f2tf(v0)),
                                       __uint_as_float(f2tf(v1)));
                *(float2*)(crow + nt * 8 + cc) = v;
            }
        }
    }
}

// ============= fused down GEMM (MoE + shared, all-atomic onto zeroed out) =============
// 1D grid: blocks [0,8192) = MoE (e = bid/1024; 32 m-tiles x 32 n-tiles),
//          blocks [8192,9216) = shared (32 m-tiles x 32 n-tiles).
// Block: 128M x 64N; warps 4(M) x 2(N); 3-stage cp.async (24KB/stage = 72KB); 2 CTAs/SM.
__global__ void __launch_bounds__(256, 2)
down_fused(float* __restrict__ out)
{
    extern __shared__ unsigned smem[];
    const int bid = blockIdx.x;
    const bool moe = (bid < 8192);
    int e = 0, my, nx;
    if (moe) { e = bid / 1024; int r = bid % 1024; my = r / 32; nx = r % 32; }
    else     { int r = bid - 8192; my = r / 32; nx = r % 32; }

    const int M  = moe ? g_cnt[e] : T_TOK;
    const int m0 = my * 128;
    if (m0 >= M) return;
    const int n0 = nx * 64;

    const float* A; int lda; const float* B; int Kd;
    if (moe) { A = g_act_moe + (size_t)e * T_TOK * IMOE; lda = IMOE;
               B = g_dwn_tf  + (size_t)e * DDIM * IMOE;  Kd = IMOE; }
    else     { A = g_act_shared; lda = ISH; B = g_sdw_tf; Kd = ISH; }

    const unsigned sbase = (unsigned)__cvta_generic_to_shared(smem);
    const int tid = threadIdx.x, lane = tid & 31, wid = tid >> 5;
    const int wm = (wid & 3) * 32, wn = (wid >> 2) * 32;

    const float* asrc[4]; int asz[4]; unsigned adst[4];
#pragma unroll
    for (int i = 0; i < 4; i++) {
        int id = tid + i * 256, row = id >> 3, ch = id & 7;
        int r = m0 + row;
        bool v = (r < M);
        asrc[i] = v ? A + (size_t)r * lda + ch * 4 : A;
        asz[i]  = v ? 16 : 0;
        adst[i] = swz(row, ch) * 16;
    }
    const float* bsrc[2]; unsigned bdst[2];
#pragma unroll
    for (int i = 0; i < 2; i++) {
        int id = tid + i * 256, row = id >> 3, ch = id & 7;
        bsrc[i] = B + (size_t)(n0 + row) * Kd + ch * 4;
        bdst[i] = swz(row, ch) * 16;
    }

    auto issue = [&](int s) {
        unsigned sb = sbase + (s % 3) * 24576;
        int koff = s * 32;
#pragma unroll
        for (int i = 0; i < 4; i++) cp16z(sb + adst[i], asrc[i] + koff, asz[i]);
#pragma unroll
        for (int i = 0; i < 2; i++) cp16(sb + 16384 + bdst[i], bsrc[i] + koff);
    };

    const int sub = lane >> 3, rr = lane & 7;
    unsigned offA[4][2], offB[4][2];
#pragma unroll
    for (int ks = 0; ks < 4; ks++) {
#pragma unroll
        for (int mt = 0; mt < 2; mt++)
            offA[ks][mt] = swz(wm + mt * 16 + (sub & 1) * 8 + rr, 2 * ks + (sub >> 1)) * 16;
#pragma unroll
        for (int jg = 0; jg < 2; jg++)
            offB[ks][jg] = swz(wn + (jg * 2 + (sub >> 1)) * 8 + rr, 2 * ks + (sub & 1)) * 16;
    }

    float c[2][4][4] = {};
    const int S = Kd / 32;

    issue(0); CP_COMMIT();
    issue(1); CP_COMMIT();

#pragma unroll 1
    for (int s = 0; s < S; s++) {
        if (s + 1 < S) { CP_WAIT1(); } else { CP_WAIT0(); }
        __syncthreads();
        unsigned sb = sbase + (s % 3) * 24576;
#pragma unroll
        for (int ks = 0; ks < 4; ks++) {
            unsigned a[2][4], bb[4][2];
#pragma unroll
            for (int mt = 0; mt < 2; mt++)
                ldsm4(a[mt][0], a[mt][1], a[mt][2], a[mt][3], sb + offA[ks][mt]);
#pragma unroll
            for (int jg = 0; jg < 2; jg++)
                ldsm4(bb[2*jg][0], bb[2*jg][1], bb[2*jg+1][0], bb[2*jg+1][1],
                      sb + 16384 + offB[ks][jg]);
#pragma unroll
            for (int mt = 0; mt < 2; mt++)
#pragma unroll
                for (int nt = 0; nt < 4; nt++)
                    mma8(c[mt][nt], a[mt], bb[nt]);
        }
        if (s + 2 < S) { issue(s + 2); CP_COMMIT(); }
    }

    // epilogue: vectorized atomic accumulate onto zeroed output
    const int rr2 = lane >> 2, cc = (lane & 3) * 2;
#pragma unroll
    for (int mt = 0; mt < 2; mt++) {
#pragma unroll
        for (int h2 = 0; h2 < 2; h2++) {
            int r = m0 + wm + mt * 16 + rr2 + h2 * 8;
            if (r >= M) continue;
            float wt; float* orow;
            if (moe) {
                int tok = g_idx[e * T_TOK + r];
                wt   = g_cw[e * T_TOK + r];
                orow = out + (size_t)tok * DDIM + n0 + wn;
            } else {
                wt   = g_sgate[r];
                orow = out + (size_t)r * DDIM + n0 + wn;
            }
#pragma unroll
            for (int nt = 0; nt < 4; nt++)
                red2(orow + nt * 8 + cc,
                     wt * c[mt][nt][2*h2+0], wt * c[mt][nt][2*h2+1]);
        }
    }
}

// ---------------- launch ----------------
extern "C" void kernel_launch(void* const* d_in, const int* in_sizes, int n_in,
                              void* d_out, int out_size) {
    const float* h    = (const float*)d_in[0];  // [T, D]
    const float* gw   = (const float*)d_in[1];  // [E, D]
    const float* gup  = (const float*)d_in[2];  // [E, 2I, D]
    const float* dwn  = (const float*)d_in[3];  // [E, D, I]
    const float* sgw  = (const float*)d_in[4];  // [IS, D]
    const float* suw  = (const float*)d_in[5];  // [IS, D]
    const float* sdw  = (const float*)d_in[6];  // [D, IS]
    const float* segw = (const float*)d_in[7];  // [1, D]
    float* out = (float*)d_out;

    const int SMEM_GU = 98304;   // 96KB (3 x 32KB); 2 CTAs/SM
    const int SMEM_DN = 73728;   // 72KB (3 x 24KB); 2 CTAs/SM

    static bool init_done = false;
    if (!init_done) {
        cudaFuncSetAttribute(gateup_fused, cudaFuncAttributeMaxDynamicSharedMemorySize, SMEM_GU);
        cudaFuncSetAttribute(down_fused,   cudaFuncAttributeMaxDynamicSharedMemorySize, SMEM_DN);
        init_done = true;
    }

    // zero output (down_fused accumulates atomically into it)
    cudaMemsetAsync(out, 0, (size_t)out_size * sizeof(float));

    zero_cnt_kernel<<<1, 32>>>();

    // fused: tf32 conversion of h + all weights (y<6) and router (y==6)
    prep_kernel<<<dim3(T_TOK, 7), 256>>>(h, gup, dwn, sgw, suw, sdw, gw, segw);

    // fused gate/up: MoE (blocks 0..3071) + shared (3072..5119)
    gateup_fused<<<5120, 256, SMEM_GU>>>();

    // fused down: MoE (0..8191) + shared (8192..9215), all-atomic epilogues
    down_fused<<<9216, 256, SMEM_DN>>>(out);
}

// round 9
// speedup vs baseline: 1.1803x; 1.0746x over previous
#include <cuda_runtime.h>
#include <math.h>

#define T_TOK 4096   // B*L tokens
#define DDIM  2048   // hidden dim
#define NEXP  8      // experts
#define IMOE  768    // expert intermediate
#define ISH   4096   // shared expert intermediate

// ---------------- device scratch (static, no allocations) ----------------
__device__ float g_act_shared[(size_t)T_TOK * ISH];            // tf32 bits
__device__ float g_act_moe[(size_t)NEXP * T_TOK * IMOE];       // tf32 bits
__device__ int   g_idx[NEXP * T_TOK];
__device__ float g_cw[NEXP * T_TOK];
__device__ int   g_cnt[NEXP];
__device__ float g_sgate[T_TOK];
// tf32-converted operands
__device__ float g_h_tf[(size_t)T_TOK * DDIM];
__device__ float g_gup_tf[(size_t)NEXP * 2 * IMOE * DDIM];
__device__ float g_dwn_tf[(size_t)NEXP * DDIM * IMOE];
__device__ float g_sgw_tf[(size_t)ISH * DDIM];
__device__ float g_suw_tf[(size_t)ISH * DDIM];
__device__ float g_sdw_tf[(size_t)DDIM * ISH];

// ---------------- helpers ----------------
__device__ __forceinline__ float silu_f(float x) { return x / (1.f + expf(-x)); }

__device__ __forceinline__ unsigned f2tf(float x) {
    unsigned u;
    asm("cvt.rna.tf32.f32 %0, %1;" : "=r"(u) : "f"(x));
    return u;
}
__device__ __forceinline__ void ldsm4(unsigned& r0, unsigned& r1,
                                      unsigned& r2, unsigned& r3, unsigned addr) {
    asm volatile("ldmatrix.sync.aligned.m8n8.x4.shared.b16 {%0,%1,%2,%3}, [%4];"
                 : "=r"(r0), "=r"(r1), "=r"(r2), "=r"(r3) : "r"(addr));
}
__device__ __forceinline__ void mma8(float* c, const unsigned* a, const unsigned* b) {
    asm volatile("mma.sync.aligned.m16n8k8.row.col.f32.tf32.tf32.f32 "
                 "{%0,%1,%2,%3}, {%4,%5,%6,%7}, {%8,%9}, {%0,%1,%2,%3};"
                 : "+f"(c[0]), "+f"(c[1]), "+f"(c[2]), "+f"(c[3])
                 : "r"(a[0]), "r"(a[1]), "r"(a[2]), "r"(a[3]),
                   "r"(b[0]), "r"(b[1]));
}
__device__ __forceinline__ void cp16(unsigned dst, const void* src) {
    asm volatile("cp.async.cg.shared.global [%0], [%1], 16;"
                 :: "r"(dst), "l"(src) : "memory");
}
__device__ __forceinline__ void cp16z(unsigned dst, const void* src, int sz) {
    asm volatile("cp.async.cg.shared.global [%0], [%1], 16, %2;"
                 :: "r"(dst), "l"(src), "r"(sz) : "memory");
}
#define CP_COMMIT() asm volatile("cp.async.commit_group;" ::: "memory")
#define CP_WAIT1()  asm volatile("cp.async.wait_group 1;" ::: "memory")
#define CP_WAIT0()  asm volatile("cp.async.wait_group 0;" ::: "memory")

// vectorized global float2 atomic add (sm_90+)
__device__ __forceinline__ void red2(float* a, float x, float y) {
    asm volatile("red.global.add.v2.f32 [%0], {%1,%2};"
                 :: "l"(a), "f"(x), "f"(y) : "memory");
}

// XOR-swizzled 16B-chunk index for a [rows x 32-float] k-tile (8 chunks/row)
__device__ __forceinline__ int swz(int row, int chunk) {
    return row * 8 + (chunk ^ (row & 7));
}

// ---------------- small kernels ----------------
__global__ void zero_cnt_kernel() {
    if (threadIdx.x < NEXP) g_cnt[threadIdx.x] = 0;
}

// Fused prep: grid (4096, 7). y<6 = tf32 conversion slices; y==6 = router.
__global__ void prep_kernel(const float* __restrict__ h,
                            const float* __restrict__ gup,
                            const float* __restrict__ dwn,
                            const float* __restrict__ sgw,
                            const float* __restrict__ suw,
                            const float* __restrict__ sdw,
                            const float* __restrict__ gw,
                            const float* __restrict__ segw) {
    const int tid = threadIdx.x;   // 256
    if (blockIdx.y < 6) {
        const float4* src; float4* dst; size_t n4;
        switch (blockIdx.y) {
            case 0: src=(const float4*)h;   dst=(float4*)g_h_tf;   n4=(size_t)T_TOK*DDIM/4; break;
            case 1: src=(const float4*)gup; dst=(float4*)g_gup_tf; n4=(size_t)NEXP*2*IMOE*DDIM/4; break;
            case 2: src=(const float4*)dwn; dst=(float4*)g_dwn_tf; n4=(size_t)NEXP*DDIM*IMOE/4; break;
            case 3: src=(const float4*)sgw; dst=(float4*)g_sgw_tf; n4=(size_t)ISH*DDIM/4; break;
            case 4: src=(const float4*)suw; dst=(float4*)g_suw_tf; n4=(size_t)ISH*DDIM/4; break;
            default:src=(const float4*)sdw; dst=(float4*)g_sdw_tf; n4=(size_t)DDIM*ISH/4; break;
        }
        size_t i = (size_t)blockIdx.x * 256 + tid;
        size_t stride = (size_t)gridDim.x * 256;
        for (; i < n4; i += stride) {
            float4 v = src[i];
            uint4 q = make_uint4(f2tf(v.x), f2tf(v.y), f2tf(v.z), f2tf(v.w));
            ((uint4*)dst)[i] = q;
        }
        return;
    }
    // ---- router (one block per token, 256 threads) ----
    const int t = blockIdx.x;
    float acc[9];
#pragma unroll
    for (int e = 0; e < 9; e++) acc[e] = 0.f;
    const float* hp = h + (size_t)t * DDIM;
    for (int d = tid; d < DDIM; d += 256) {
        float hv = hp[d];
#pragma unroll
        for (int e = 0; e < 8; e++) acc[e] += hv * gw[e * DDIM + d];
        acc[8] += hv * segw[d];
    }
#pragma unroll
    for (int e = 0; e < 9; e++) {
#pragma unroll
        for (int off = 16; off > 0; off >>= 1)
            acc[e] += __shfl_down_sync(0xffffffffu, acc[e], off);
    }
    __shared__ float s[9][8];
    int warp = tid >> 5, lane = tid & 31;
    if (lane == 0) {
#pragma unroll
        for (int e = 0; e < 9; e++) s[e][warp] = acc[e];
    }
    __syncthreads();
    if (tid == 0) {
        float logits[9];
#pragma unroll
        for (int e = 0; e < 9; e++) {
            float v = 0.f;
#pragma unroll
            for (int w2 = 0; w2 < 8; w2++) v += s[e][w2];
            logits[e] = v;
        }
        int i1 = 0; float l1 = logits[0];
#pragma unroll
        for (int e = 1; e < 8; e++)
            if (logits[e] > l1) { l1 = logits[e]; i1 = e; }
        int i2 = -1; float l2 = -3.0e38f;
#pragma unroll
        for (int e = 0; e < 8; e++)
            if (e != i1 && logits[e] > l2) { l2 = logits[e]; i2 = e; }
        float w1 = 1.f / (1.f + expf(l2 - l1));
        float w2 = 1.f - w1;
        int r1 = atomicAdd(&g_cnt[i1], 1);
        g_idx[i1 * T_TOK + r1] = t;  g_cw[i1 * T_TOK + r1] = w1;
        int r2 = atomicAdd(&g_cnt[i2], 1);
        g_idx[i2 * T_TOK + r2] = t;  g_cw[i2 * T_TOK + r2] = w2;
        g_sgate[t] = 1.f / (1.f + expf(-logits[8]));
    }
}

// ============= fused gate/up GEMM (shared first, then MoE) =============
// 1D grid: blocks [0,2048) = shared (32 m-tiles x 64 n-tiles),
//          blocks [2048,5120) = MoE (e = r/384; 32 m-tiles x 12 n-tiles).
// Block: 128M x 64N per matrix; warps 4(M) x 2(N); 3-stage cp.async; 2 CTAs/SM.
// Stage: [A 16KB][G 8KB][U 8KB] = 32KB; 3 stages = 96KB.
__global__ void __launch_bounds__(256, 2)
gateup_fused()
{
    extern __shared__ unsigned smem[];
    const int bid = blockIdx.x;
    const bool gather = (bid >= 2048);
    int e = 0, my, nx;
    if (!gather) { my = bid >> 6; nx = bid & 63; }
    else { int r = bid - 2048; e = r / 384; int q = r % 384; my = q / 12; nx = q % 12; }

    const int M  = gather ? g_cnt[e] : T_TOK;
    const int m0 = my * 128;
    if (m0 >= M) return;
    const int n0 = nx * 64;

    const float *Bg, *Bu; float* C; int ldc;
    if (gather) {
        Bg = g_gup_tf + (size_t)e * 2 * IMOE * DDIM;
        Bu = Bg + (size_t)IMOE * DDIM;
        C  = g_act_moe + (size_t)e * T_TOK * IMOE;  ldc = IMOE;
    } else {
        Bg = g_sgw_tf;  Bu = g_suw_tf;
        C  = g_act_shared;  ldc = ISH;
    }

    const unsigned sbase = (unsigned)__cvta_generic_to_shared(smem);
    const int tid = threadIdx.x, lane = tid & 31, wid = tid >> 5;
    const int wm = (wid & 3) * 32, wn = (wid >> 2) * 32;

    const float* asrc[4]; int asz[4]; unsigned adst[4];
#pragma unroll
    for (int i = 0; i < 4; i++) {
        int id = tid + i * 256, row = id >> 3, ch = id & 7;
        int r = m0 + row;
        bool v = gather ? (r < M) : true;
        const float* arow;
        if (gather) arow = v ? g_h_tf + (size_t)g_idx[e * T_TOK + r] * DDIM : g_h_tf;
        else        arow = g_h_tf + (size_t)r * DDIM;
        asrc[i] = arow + ch * 4;
        asz[i]  = v ? 16 : 0;
        adst[i] = swz(row, ch) * 16;
    }
    const float* gsrc[2]; const float* usrc[2]; unsigned bdst[2];
#pragma unroll
    for (int i = 0; i < 2; i++) {
        int id = tid + i * 256, row = id >> 3, ch = id & 7;
        gsrc[i] = Bg + (size_t)(n0 + row) * DDIM + ch * 4;
        usrc[i] = Bu + (size_t)(n0 + row) * DDIM + ch * 4;
        bdst[i] = swz(row, ch) * 16;
    }

    auto issue = [&](int s) {
        unsigned sb = sbase + (s % 3) * 32768;
        int koff = s * 32;
#pragma unroll
        for (int i = 0; i < 4; i++) cp16z(sb + adst[i], asrc[i] + koff, asz[i]);
#pragma unroll
        for (int i = 0; i < 2; i++) cp16(sb + 16384 + bdst[i], gsrc[i] + koff);
#pragma unroll
        for (int i = 0; i < 2; i++) cp16(sb + 24576 + bdst[i], usrc[i] + koff);
    };

    const int sub = lane >> 3, rr = lane & 7;
    unsigned offA[4], offB[4];
#pragma unroll
    for (int ks = 0; ks < 4; ks++) {
        offA[ks] = swz(wm + (sub & 1) * 8 + rr, 2 * ks + (sub >> 1)) * 16;
        offB[ks] = swz(wn + (sub >> 1) * 8 + rr, 2 * ks + (sub & 1)) * 16;
    }

    float cg[2][4][4] = {}, cu[2][4][4] = {};
    const int S = DDIM / 32;

    issue(0); CP_COMMIT();
    issue(1); CP_COMMIT();

#pragma unroll 1
    for (int s = 0; s < S; s++) {
        if (s + 1 < S) { CP_WAIT1(); } else { CP_WAIT0(); }
        __syncthreads();
        unsigned sb = sbase + (s % 3) * 32768;
#pragma unroll
        for (int ks = 0; ks < 4; ks++) {
            unsigned a[2][4], bg[4][2], bu[4][2];
#pragma unroll
            for (int mt = 0; mt < 2; mt++)
                ldsm4(a[mt][0], a[mt][1], a[mt][2], a[mt][3],
                      sb + offA[ks] + mt * 2048);
#pragma unroll
            for (int jg = 0; jg < 2; jg++) {
                ldsm4(bg[2*jg][0], bg[2*jg][1], bg[2*jg+1][0], bg[2*jg+1][1],
                      sb + 16384 + offB[ks] + jg * 2048);
                ldsm4(bu[2*jg][0], bu[2*jg][1], bu[2*jg+1][0], bu[2*jg+1][1],
                      sb + 24576 + offB[ks] + jg * 2048);
            }
#pragma unroll
            for (int mt = 0; mt < 2; mt++)
#pragma unroll
                for (int nt = 0; nt < 4; nt++) {
                    mma8(cg[mt][nt], a[mt], bg[nt]);
                    mma8(cu[mt][nt], a[mt], bu[nt]);
                }
        }
        if (s + 2 < S) { issue(s + 2); CP_COMMIT(); }
    }

    // epilogue: silu(g)*u as tf32 bits (down GEMM A-side needs no cvt)
    const int rr2 = lane >> 2, cc = (lane & 3) * 2;
#pragma unroll
    for (int mt = 0; mt < 2; mt++) {
#pragma unroll
        for (int h2 = 0; h2 < 2; h2++) {
            int r = m0 + wm + mt * 16 + rr2 + h2 * 8;
            if (gather && r >= M) continue;
            float* crow = C + (size_t)r * ldc + n0 + wn;
#pragma unroll
            for (int nt = 0; nt < 4; nt++) {
                float v0 = silu_f(cg[mt][nt][2*h2+0]) * cu[mt][nt][2*h2+0];
                float v1 = silu_f(cg[mt][nt][2*h2+1]) * cu[mt][nt][2*h2+1];
                float2 v = make_float2(__uint_as_float(f2tf(v0)),
                                       __uint_as_float(f2tf(v1)));
                *(float2*)(crow + nt * 8 + cc) = v;
            }
        }
    }
}

// ============= fused down GEMM (128x128 tile; shared first, then MoE) =============
// 1D grid: blocks [0,512) = shared (32 m-tiles x 16 n-tiles, K=4096),
//          blocks [512,4608) = MoE (e = r/512; 32 m-tiles x 16 n-tiles, K=768).
// Block: 128M x 128N; warps 4(M) x 2(N): warp tile 32x64 (64 accum regs).
// Stage: [A 16KB][B 16KB] = 32KB; 3 stages = 96KB; 2 CTAs/SM.
__global__ void __launch_bounds__(256, 2)
down_fused(float* __restrict__ out)
{
    extern __shared__ unsigned smem[];
    const int bid = blockIdx.x;
    const bool moe = (bid >= 512);
    int e = 0, my, nx;
    if (!moe) { my = bid >> 4; nx = bid & 15; }
    else { int r = bid - 512; e = r >> 9; int q = r & 511; my = q >> 4; nx = q & 15; }

    const int M  = moe ? g_cnt[e] : T_TOK;
    const int m0 = my * 128;
    if (m0 >= M) return;
    const int n0 = nx * 128;

    const float* A; int lda; const float* B; int Kd;
    if (moe) { A = g_act_moe + (size_t)e * T_TOK * IMOE; lda = IMOE;
               B = g_dwn_tf  + (size_t)e * DDIM * IMOE;  Kd = IMOE; }
    else     { A = g_act_shared; lda = ISH; B = g_sdw_tf; Kd = ISH; }

    const unsigned sbase = (unsigned)__cvta_generic_to_shared(smem);
    const int tid = threadIdx.x, lane = tid & 31, wid = tid >> 5;
    const int wm = (wid & 3) * 32, wn = (wid >> 2) * 64;

    const float* asrc[4]; int asz[4]; unsigned adst[4];
    const float* bsrc[4]; unsigned bdst[4];
#pragma unroll
    for (int i = 0; i < 4; i++) {
        int id = tid + i * 256, row = id >> 3, ch = id & 7;
        int r = m0 + row;
        bool v = (r < M);
        asrc[i] = v ? A + (size_t)r * lda + ch * 4 : A;
        asz[i]  = v ? 16 : 0;
        adst[i] = swz(row, ch) * 16;
        bsrc[i] = B + (size_t)(n0 + row) * Kd + ch * 4;
        bdst[i] = 16384 + swz(row, ch) * 16;
    }

    auto issue = [&](int s) {
        unsigned sb = sbase + (s % 3) * 32768;
        int koff = s * 32;
#pragma unroll
        for (int i = 0; i < 4; i++) cp16z(sb + adst[i], asrc[i] + koff, asz[i]);
#pragma unroll
        for (int i = 0; i < 4; i++) cp16(sb + bdst[i], bsrc[i] + koff);
    };

    const int sub = lane >> 3, rr = lane & 7;
    unsigned offA[4], offB[4];
#pragma unroll
    for (int ks = 0; ks < 4; ks++) {
        offA[ks] = swz(wm + (sub & 1) * 8 + rr, 2 * ks + (sub >> 1)) * 16;
        offB[ks] = 16384 + swz(wn + (sub >> 1) * 8 + rr, 2 * ks + (sub & 1)) * 16;
    }

    float c[2][8][4] = {};
    const int S = Kd / 32;

    issue(0); CP_COMMIT();
    issue(1); CP_COMMIT();

#pragma unroll 1
    for (int s = 0; s < S; s++) {
        if (s + 1 < S) { CP_WAIT1(); } else { CP_WAIT0(); }
        __syncthreads();
        unsigned sb = sbase + (s % 3) * 32768;
#pragma unroll
        for (int ks = 0; ks < 4; ks++) {
            unsigned a[2][4], bb[8][2];
#pragma unroll
            for (int mt = 0; mt < 2; mt++)
                ldsm4(a[mt][0], a[mt][1], a[mt][2], a[mt][3],
                      sb + offA[ks] + mt * 2048);
#pragma unroll
            for (int jg = 0; jg < 4; jg++)
                ldsm4(bb[2*jg][0], bb[2*jg][1], bb[2*jg+1][0], bb[2*jg+1][1],
                      sb + offB[ks] + jg * 2048);
#pragma unroll
            for (int mt = 0; mt < 2; mt++)
#pragma unroll
                for (int nt = 0; nt < 8; nt++)
                    mma8(c[mt][nt], a[mt], bb[nt]);
        }
        if (s + 2 < S) { issue(s + 2); CP_COMMIT(); }
    }

    // epilogue: vectorized atomic accumulate onto zeroed output
    const int rr2 = lane >> 2, cc = (lane & 3) * 2;
#pragma unroll
    for (int mt = 0; mt < 2; mt++) {
#pragma unroll
        for (int h2 = 0; h2 < 2; h2++) {
            int r = m0 + wm + mt * 16 + rr2 + h2 * 8;
            if (r >= M) continue;
            float wt; float* orow;
            if (moe) {
                int tok = g_idx[e * T_TOK + r];
                wt   = g_cw[e * T_TOK + r];
                orow = out + (size_t)tok * DDIM + n0 + wn;
            } else {
                wt   = g_sgate[r];
                orow = out + (size_t)r * DDIM + n0 + wn;
            }
#pragma unroll
            for (int nt = 0; nt < 8; nt++)
                red2(orow + nt * 8 + cc,
                     wt * c[mt][nt][2*h2+0], wt * c[mt][nt][2*h2+1]);
        }
    }
}

// ---------------- launch ----------------
extern "C" void kernel_launch(void* const* d_in, const int* in_sizes, int n_in,
                              void* d_out, int out_size) {
    const float* h    = (const float*)d_in[0];  // [T, D]
    const float* gw   = (const float*)d_in[1];  // [E, D]
    const float* gup  = (const float*)d_in[2];  // [E, 2I, D]
    const float* dwn  = (const float*)d_in[3];  // [E, D, I]
    const float* sgw  = (const float*)d_in[4];  // [IS, D]
    const float* suw  = (const float*)d_in[5];  // [IS, D]
    const float* sdw  = (const float*)d_in[6];  // [D, IS]
    const float* segw = (const float*)d_in[7];  // [1, D]
    float* out = (float*)d_out;

    const int SMEM_GU = 98304;   // 96KB (3 x 32KB); 2 CTAs/SM
    const int SMEM_DN = 98304;   // 96KB (3 x 32KB); 2 CTAs/SM

    static bool init_done = false;
    if (!init_done) {
        cudaFuncSetAttribute(gateup_fused, cudaFuncAttributeMaxDynamicSharedMemorySize, SMEM_GU);
        cudaFuncSetAttribute(down_fused,   cudaFuncAttributeMaxDynamicSharedMemorySize, SMEM_DN);
        init_done = true;
    }

    // zero output (down_fused accumulates atomically into it)
    cudaMemsetAsync(out, 0, (size_t)out_size * sizeof(float));

    zero_cnt_kernel<<<1, 32>>>();

    // fused: tf32 conversion of h + all weights (y<6) and router (y==6)
    prep_kernel<<<dim3(T_TOK, 7), 256>>>(h, gup, dwn, sgw, suw, sdw, gw, segw);

    // fused gate/up: shared (blocks 0..2047) + MoE (2048..5119)
    gateup_fused<<<5120, 256, SMEM_GU>>>();

    // fused down (128x128 tiles): shared (0..511) + MoE (512..4607)
    down_fused<<<4608, 256, SMEM_DN>>>(out);
}

// round 10
// speedup vs baseline: 2.1081x; 1.7861x over previous
#include <cuda_runtime.h>
#include <cuda_fp16.h>
#include <math.h>

#define T_TOK 4096   // B*L tokens
#define DDIM  2048   // hidden dim
#define NEXP  8      // experts
#define IMOE  768    // expert intermediate
#define ISH   4096   // shared expert intermediate

// ---------------- device scratch (static, no allocations) ----------------
__device__ __half g_act_shared[(size_t)T_TOK * ISH];
__device__ __half g_act_moe[(size_t)NEXP * T_TOK * IMOE];
__device__ int    g_idx[NEXP * T_TOK];
__device__ float  g_cw[NEXP * T_TOK];
__device__ int    g_cnt[NEXP];
__device__ float  g_sgate[T_TOK];
// fp16-converted operands
__device__ __half g_h_h[(size_t)T_TOK * DDIM];
__device__ __half g_gup_h[(size_t)NEXP * 2 * IMOE * DDIM];
__device__ __half g_dwn_h[(size_t)NEXP * DDIM * IMOE];
__device__ __half g_sgw_h[(size_t)ISH * DDIM];
__device__ __half g_suw_h[(size_t)ISH * DDIM];
__device__ __half g_sdw_h[(size_t)DDIM * ISH];

// ---------------- helpers ----------------
__device__ __forceinline__ float silu_f(float x) { return x / (1.f + expf(-x)); }

__device__ __forceinline__ void ldsm4(unsigned& r0, unsigned& r1,
                                      unsigned& r2, unsigned& r3, unsigned addr) {
    asm volatile("ldmatrix.sync.aligned.m8n8.x4.shared.b16 {%0,%1,%2,%3}, [%4];"
                 : "=r"(r0), "=r"(r1), "=r"(r2), "=r"(r3) : "r"(addr));
}
// m16n8k16 fp16 mma, fp32 accum
__device__ __forceinline__ void mma16(float* c, const unsigned* a, const unsigned* b) {
    asm volatile("mma.sync.aligned.m16n8k16.row.col.f32.f16.f16.f32 "
                 "{%0,%1,%2,%3}, {%4,%5,%6,%7}, {%8,%9}, {%0,%1,%2,%3};"
                 : "+f"(c[0]), "+f"(c[1]), "+f"(c[2]), "+f"(c[3])
                 : "r"(a[0]), "r"(a[1]), "r"(a[2]), "r"(a[3]),
                   "r"(b[0]), "r"(b[1]));
}
__device__ __forceinline__ void cp16(unsigned dst, const void* src) {
    asm volatile("cp.async.cg.shared.global [%0], [%1], 16;"
                 :: "r"(dst), "l"(src) : "memory");
}
__device__ __forceinline__ void cp16z(unsigned dst, const void* src, int sz) {
    asm volatile("cp.async.cg.shared.global [%0], [%1], 16, %2;"
                 :: "r"(dst), "l"(src), "r"(sz) : "memory");
}
#define CP_COMMIT() asm volatile("cp.async.commit_group;" ::: "memory")
#define CP_WAIT1()  asm volatile("cp.async.wait_group 1;" ::: "memory")
#define CP_WAIT0()  asm volatile("cp.async.wait_group 0;" ::: "memory")

// vectorized global float2 atomic add (sm_90+)
__device__ __forceinline__ void red2(float* a, float x, float y) {
    asm volatile("red.global.add.v2.f32 [%0], {%1,%2};"
                 :: "l"(a), "f"(x), "f"(y) : "memory");
}

// XOR-swizzled 16B-chunk index for a [rows x 128B] tile (8 chunks/row)
__device__ __forceinline__ int swz(int row, int chunk) {
    return row * 8 + (chunk ^ (row & 7));
}

// ---------------- small kernels ----------------
__global__ void zero_cnt_kernel() {
    if (threadIdx.x < NEXP) g_cnt[threadIdx.x] = 0;
}

// Fused prep: grid (4096, 7). y<6 = fp16 conversion slices; y==6 = router.
__global__ void prep_kernel(const float* __restrict__ h,
                            const float* __restrict__ gup,
                            const float* __restrict__ dwn,
                            const float* __restrict__ sgw,
                            const float* __restrict__ suw,
                            const float* __restrict__ sdw,
                            const float* __restrict__ gw,
                            const float* __restrict__ segw) {
    const int tid = threadIdx.x;   // 256
    if (blockIdx.y < 6) {
        const float4* src; uint2* dst; size_t n4;
        switch (blockIdx.y) {
            case 0: src=(const float4*)h;   dst=(uint2*)g_h_h;   n4=(size_t)T_TOK*DDIM/4; break;
            case 1: src=(const float4*)gup; dst=(uint2*)g_gup_h; n4=(size_t)NEXP*2*IMOE*DDIM/4; break;
            case 2: src=(const float4*)dwn; dst=(uint2*)g_dwn_h; n4=(size_t)NEXP*DDIM*IMOE/4; break;
            case 3: src=(const float4*)sgw; dst=(uint2*)g_sgw_h; n4=(size_t)ISH*DDIM/4; break;
            case 4: src=(const float4*)suw; dst=(uint2*)g_suw_h; n4=(size_t)ISH*DDIM/4; break;
            default:src=(const float4*)sdw; dst=(uint2*)g_sdw_h; n4=(size_t)DDIM*ISH/4; break;
        }
        size_t i = (size_t)blockIdx.x * 256 + tid;
        size_t stride = (size_t)gridDim.x * 256;
        for (; i < n4; i += stride) {
            float4 v = src[i];
            __half2 lo = __floats2half2_rn(v.x, v.y);
            __half2 hi = __floats2half2_rn(v.z, v.w);
            uint2 q;
            q.x = *(unsigned*)&lo;
            q.y = *(unsigned*)&hi;
            dst[i] = q;
        }
        return;
    }
    // ---- router (one block per token, 256 threads, fp32) ----
    const int t = blockIdx.x;
    float acc[9];
#pragma unroll
    for (int e = 0; e < 9; e++) acc[e] = 0.f;
    const float* hp = h + (size_t)t * DDIM;
    for (int d = tid; d < DDIM; d += 256) {
        float hv = hp[d];
#pragma unroll
        for (int e = 0; e < 8; e++) acc[e] += hv * gw[e * DDIM + d];
        acc[8] += hv * segw[d];
    }
#pragma unroll
    for (int e = 0; e < 9; e++) {
#pragma unroll
        for (int off = 16; off > 0; off >>= 1)
            acc[e] += __shfl_down_sync(0xffffffffu, acc[e], off);
    }
    __shared__ float s[9][8];
    int warp = tid >> 5, lane = tid & 31;
    if (lane == 0) {
#pragma unroll
        for (int e = 0; e < 9; e++) s[e][warp] = acc[e];
    }
    __syncthreads();
    if (tid == 0) {
        float logits[9];
#pragma unroll
        for (int e = 0; e < 9; e++) {
            float v = 0.f;
#pragma unroll
            for (int w2 = 0; w2 < 8; w2++) v += s[e][w2];
            logits[e] = v;
        }
        int i1 = 0; float l1 = logits[0];
#pragma unroll
        for (int e = 1; e < 8; e++)
            if (logits[e] > l1) { l1 = logits[e]; i1 = e; }
        int i2 = -1; float l2 = -3.0e38f;
#pragma unroll
        for (int e = 0; e < 8; e++)
            if (e != i1 && logits[e] > l2) { l2 = logits[e]; i2 = e; }
        float w1 = 1.f / (1.f + expf(l2 - l1));
        float w2 = 1.f - w1;
        int r1 = atomicAdd(&g_cnt[i1], 1);
        g_idx[i1 * T_TOK + r1] = t;  g_cw[i1 * T_TOK + r1] = w1;
        int r2 = atomicAdd(&g_cnt[i2], 1);
        g_idx[i2 * T_TOK + r2] = t;  g_cw[i2 * T_TOK + r2] = w2;
        g_sgate[t] = 1.f / (1.f + expf(-logits[8]));
    }
}

// ============= fused gate/up GEMM (fp16; shared first, then MoE) =============
// 1D grid: [0,2048) shared (32 m x 64 n), [2048,5120) MoE (e=r/384; 32 m x 12 n).
// Block 128M x 64N per matrix; warps 4(M) x 2(N): warp tile 32x32 per matrix.
// K-stage = 64 halfs (128 B/row). Stage: [A 16KB][G 8KB][U 8KB]=32KB; 3 stages; 2 CTAs/SM.
__global__ void __launch_bounds__(256, 2)
gateup_fused()
{
    extern __shared__ unsigned smem[];
    const int bid = blockIdx.x;
    const bool gather = (bid >= 2048);
    int e = 0, my, nx;
    if (!gather) { my = bid >> 6; nx = bid & 63; }
    else { int r = bid - 2048; e = r / 384; int q = r % 384; my = q / 12; nx = q % 12; }

    const int M  = gather ? g_cnt[e] : T_TOK;
    const int m0 = my * 128;
    if (m0 >= M) return;
    const int n0 = nx * 64;

    const __half *Bg, *Bu; __half* C; int ldc;
    if (gather) {
        Bg = g_gup_h + (size_t)e * 2 * IMOE * DDIM;
        Bu = Bg + (size_t)IMOE * DDIM;
        C  = g_act_moe + (size_t)e * T_TOK * IMOE;  ldc = IMOE;
    } else {
        Bg = g_sgw_h;  Bu = g_suw_h;
        C  = g_act_shared;  ldc = ISH;
    }

    const unsigned sbase = (unsigned)__cvta_generic_to_shared(smem);
    const int tid = threadIdx.x, lane = tid & 31, wid = tid >> 5;
    const int wm = (wid & 3) * 32, wn = (wid >> 2) * 32;

    // cp.async setup: A tile 128 rows x 128B (4 chunks/thread); G,U 64 rows (2 each)
    const __half* asrc[4]; int asz[4]; unsigned adst[4];
#pragma unroll
    for (int i = 0; i < 4; i++) {
        int id = tid + i * 256, row = id >> 3, ch = id & 7;
        int r = m0 + row;
        bool v = gather ? (r < M) : true;
        const __half* arow;
        if (gather) arow = v ? g_h_h + (size_t)g_idx[e * T_TOK + r] * DDIM : g_h_h;
        else        arow = g_h_h + (size_t)r * DDIM;
        asrc[i] = arow + ch * 8;
        asz[i]  = v ? 16 : 0;
        adst[i] = swz(row, ch) * 16;
    }
    const __half* gsrc[2]; const __half* usrc[2]; unsigned bdst[2];
#pragma unroll
    for (int i = 0; i < 2; i++) {
        int id = tid + i * 256, row = id >> 3, ch = id & 7;
        gsrc[i] = Bg + (size_t)(n0 + row) * DDIM + ch * 8;
        usrc[i] = Bu + (size_t)(n0 + row) * DDIM + ch * 8;
        bdst[i] = swz(row, ch) * 16;
    }

    auto issue = [&](int s) {
        unsigned sb = sbase + (s % 3) * 32768;
        int koff = s * 64;   // halfs
#pragma unroll
        for (int i = 0; i < 4; i++) cp16z(sb + adst[i], asrc[i] + koff, asz[i]);
#pragma unroll
        for (int i = 0; i < 2; i++) cp16(sb + 16384 + bdst[i], gsrc[i] + koff);
#pragma unroll
        for (int i = 0; i < 2; i++) cp16(sb + 24576 + bdst[i], usrc[i] + koff);
    };

    // fragment offsets (m16n8k16):
    // A: row = (lane&7) + ((lane>>3)&1)*8, chunk = 2*ks + (lane>>4)
    // B: row = (lane&7) + (lane>>4)*8,    chunk = 2*ks + ((lane>>3)&1)
    const int l7 = lane & 7, lb3 = (lane >> 3) & 1, lb4 = lane >> 4;
    unsigned offA[4], offB[4];
#pragma unroll
    for (int ks = 0; ks < 4; ks++) {
        offA[ks] = swz(wm + l7 + lb3 * 8, 2 * ks + lb4) * 16;
        offB[ks] = swz(wn + l7 + lb4 * 8, 2 * ks + lb3) * 16;
    }

    float cg[2][4][4] = {}, cu[2][4][4] = {};
    const int S = DDIM / 64;   // 32

    issue(0); CP_COMMIT();
    issue(1); CP_COMMIT();

#pragma unroll 1
    for (int s = 0; s < S; s++) {
        if (s + 1 < S) { CP_WAIT1(); } else { CP_WAIT0(); }
        __syncthreads();
        unsigned sb = sbase + (s % 3) * 32768;
#pragma unroll
        for (int ks = 0; ks < 4; ks++) {
            unsigned a[2][4], bg[4][2], bu[4][2];
#pragma unroll
            for (int mt = 0; mt < 2; mt++)
                ldsm4(a[mt][0], a[mt][1], a[mt][2], a[mt][3],
                      sb + offA[ks] + mt * 2048);
#pragma unroll
            for (int jg = 0; jg < 2; jg++) {   // each ldsm4 covers 16 n (2 subtiles)
                ldsm4(bg[2*jg][0], bg[2*jg][1], bg[2*jg+1][0], bg[2*jg+1][1],
                      sb + 16384 + offB[ks] + jg * 2048);
                ldsm4(bu[2*jg][0], bu[2*jg][1], bu[2*jg+1][0], bu[2*jg+1][1],
                      sb + 24576 + offB[ks] + jg * 2048);
            }
#pragma unroll
            for (int mt = 0; mt < 2; mt++)
#pragma unroll
                for (int nt = 0; nt < 4; nt++) {
                    mma16(cg[mt][nt], a[mt], bg[nt]);
                    mma16(cu[mt][nt], a[mt], bu[nt]);
                }
        }
        if (s + 2 < S) { issue(s + 2); CP_COMMIT(); }
    }

    // epilogue: act = fp16(silu(g)*u)
    const int rr2 = lane >> 2, cc = (lane & 3) * 2;
#pragma unroll
    for (int mt = 0; mt < 2; mt++) {
#pragma unroll
        for (int h2 = 0; h2 < 2; h2++) {
            int r = m0 + wm + mt * 16 + rr2 + h2 * 8;
            if (gather && r >= M) continue;
            __half* crow = C + (size_t)r * ldc + n0 + wn;
#pragma unroll
            for (int nt = 0; nt < 4; nt++) {
                float v0 = silu_f(cg[mt][nt][2*h2+0]) * cu[mt][nt][2*h2+0];
                float v1 = silu_f(cg[mt][nt][2*h2+1]) * cu[mt][nt][2*h2+1];
                *(__half2*)(crow + nt * 8 + cc) = __floats2half2_rn(v0, v1);
            }
        }
    }
}

// ============= fused down GEMM (fp16, 128x128 tile; shared first, then MoE) =============
// 1D grid: [0,512) shared (32 m x 16 n, K=4096), [512,4608) MoE (e=r/512; 32 m x 16 n, K=768).
// Block 128M x 128N; warps 4(M) x 2(N): warp tile 32x64 (64 accum regs).
// K-stage = 64 halfs. Stage: [A 16KB][B 16KB]=32KB; 3 stages = 96KB; 2 CTAs/SM.
__global__ void __launch_bounds__(256, 2)
down_fused(float* __restrict__ out)
{
    extern __shared__ unsigned smem[];
    const int bid = blockIdx.x;
    const bool moe = (bid >= 512);
    int e = 0, my, nx;
    if (!moe) { my = bid >> 4; nx = bid & 15; }
    else { int r = bid - 512; e = r >> 9; int q = r & 511; my = q >> 4; nx = q & 15; }

    const int M  = moe ? g_cnt[e] : T_TOK;
    const int m0 = my * 128;
    if (m0 >= M) return;
    const int n0 = nx * 128;

    const __half* A; int lda; const __half* B; int Kd;
    if (moe) { A = g_act_moe + (size_t)e * T_TOK * IMOE; lda = IMOE;
               B = g_dwn_h  + (size_t)e * DDIM * IMOE;   Kd = IMOE; }
    else     { A = g_act_shared; lda = ISH; B = g_sdw_h; Kd = ISH; }

    const unsigned sbase = (unsigned)__cvta_generic_to_shared(smem);
    const int tid = threadIdx.x, lane = tid & 31, wid = tid >> 5;
    const int wm = (wid & 3) * 32, wn = (wid >> 2) * 64;

    const __half* asrc[4]; int asz[4]; unsigned adst[4];
    const __half* bsrc[4]; unsigned bdst[4];
#pragma unroll
    for (int i = 0; i < 4; i++) {
        int id = tid + i * 256, row = id >> 3, ch = id & 7;
        int r = m0 + row;
        bool v = (r < M);
        asrc[i] = v ? A + (size_t)r * lda + ch * 8 : A;
        asz[i]  = v ? 16 : 0;
        adst[i] = swz(row, ch) * 16;
        bsrc[i] = B + (size_t)(n0 + row) * Kd + ch * 8;
        bdst[i] = 16384 + swz(row, ch) * 16;
    }

    auto issue = [&](int s) {
        unsigned sb = sbase + (s % 3) * 32768;
        int koff = s * 64;
#pragma unroll
        for (int i = 0; i < 4; i++) cp16z(sb + adst[i], asrc[i] + koff, asz[i]);
#pragma unroll
        for (int i = 0; i < 4; i++) cp16(sb + bdst[i], bsrc[i] + koff);
    };

    const int l7 = lane & 7, lb3 = (lane >> 3) & 1, lb4 = lane >> 4;
    unsigned offA[4], offB[4];
#pragma unroll
    for (int ks = 0; ks < 4; ks++) {
        offA[ks] = swz(wm + l7 + lb3 * 8, 2 * ks + lb4) * 16;
        offB[ks] = 16384 + swz(wn + l7 + lb4 * 8, 2 * ks + lb3) * 16;
    }

    float c[2][8][4] = {};
    const int S = Kd / 64;   // 12 or 64

    issue(0); CP_COMMIT();
    issue(1); CP_COMMIT();

#pragma unroll 1
    for (int s = 0; s < S; s++) {
        if (s + 1 < S) { CP_WAIT1(); } else { CP_WAIT0(); }
        __syncthreads();
        unsigned sb = sbase + (s % 3) * 32768;
#pragma unroll
        for (int ks = 0; ks < 4; ks++) {
            unsigned a[2][4], bb[8][2];
#pragma unroll
            for (int mt = 0; mt < 2; mt++)
                ldsm4(a[mt][0], a[mt][1], a[mt][2], a[mt][3],
                      sb + offA[ks] + mt * 2048);
#pragma unroll
            for (int jg = 0; jg < 4; jg++)
                ldsm4(bb[2*jg][0], bb[2*jg][1], bb[2*jg+1][0], bb[2*jg+1][1],
                      sb + offB[ks] + jg * 2048);
#pragma unroll
            for (int mt = 0; mt < 2; mt++)
#pragma unroll
                for (int nt = 0; nt < 8; nt++)
                    mma16(c[mt][nt], a[mt], bb[nt]);
        }
        if (s + 2 < S) { issue(s + 2); CP_COMMIT(); }
    }

    // epilogue: vectorized atomic accumulate onto zeroed fp32 output
    const int rr2 = lane >> 2, cc = (lane & 3) * 2;
#pragma unroll
    for (int mt = 0; mt < 2; mt++) {
#pragma unroll
        for (int h2 = 0; h2 < 2; h2++) {
            int r = m0 + wm + mt * 16 + rr2 + h2 * 8;
            if (r >= M) continue;
            float wt; float* orow;
            if (moe) {
                int tok = g_idx[e * T_TOK + r];
                wt   = g_cw[e * T_TOK + r];
                orow = out + (size_t)tok * DDIM + n0 + wn;
            } else {
                wt   = g_sgate[r];
                orow = out + (size_t)r * DDIM + n0 + wn;
            }
#pragma unroll
            for (int nt = 0; nt < 8; nt++)
                red2(orow + nt * 8 + cc,
                     wt * c[mt][nt][2*h2+0], wt * c[mt][nt][2*h2+1]);
        }
    }
}

// ---------------- launch ----------------
extern "C" void kernel_launch(void* const* d_in, const int* in_sizes, int n_in,
                              void* d_out, int out_size) {
    const float* h    = (const float*)d_in[0];  // [T, D]
    const float* gw   = (const float*)d_in[1];  // [E, D]
    const float* gup  = (const float*)d_in[2];  // [E, 2I, D]
    const float* dwn  = (const float*)d_in[3];  // [E, D, I]
    const float* sgw  = (const float*)d_in[4];  // [IS, D]
    const float* suw  = (const float*)d_in[5];  // [IS, D]
    const float* sdw  = (const float*)d_in[6];  // [D, IS]
    const float* segw = (const float*)d_in[7];  // [1, D]
    float* out = (float*)d_out;

    const int SMEM = 98304;   // 96KB (3 x 32KB); 2 CTAs/SM

    static bool init_done = false;
    if (!init_done) {
        cudaFuncSetAttribute(gateup_fused, cudaFuncAttributeMaxDynamicSharedMemorySize, SMEM);
        cudaFuncSetAttribute(down_fused,   cudaFuncAttributeMaxDynamicSharedMemorySize, SMEM);
        init_done = true;
    }

    // zero output (down_fused accumulates atomically into it)
    cudaMemsetAsync(out, 0, (size_t)out_size * sizeof(float));

    zero_cnt_kernel<<<1, 32>>>();

    // fused: fp16 conversion of h + all weights (y<6) and router (y==6)
    prep_kernel<<<dim3(T_TOK, 7), 256>>>(h, gup, dwn, sgw, suw, sdw, gw, segw);

    // fused gate/up: shared (blocks 0..2047) + MoE (2048..5119)
    gateup_fused<<<5120, 256, SMEM>>>();

    // fused down (128x128 tiles): shared (0..511) + MoE (512..4607)
    down_fused<<<4608, 256, SMEM>>>(out);
}